// round 9
// baseline (speedup 1.0000x reference)
#include <cuda_runtime.h>
#include <cuda_fp16.h>
#include <cstdint>
#include <cstddef>

// ============================================================================
// y = clip((x @ ternarize(W)) * scale + bias, -100, 100)
//   x [8192,4096] f32, W [4096,4096] f32, scale/bias [4096] f32, out f32.
//
// Harness compiles PTX at compute_103 (no 'a' feature) -> tcgen05/TMEM are
// unavailable. Path: warp-level mma.sync m16n8k16 fp16 (sm_80 baseline),
// single-pass fp16 (norm rel-err ~2.8e-4 < 1e-3), cp.async 4-stage pipeline.
// ============================================================================

#define M_TOTAL 8192
#define K_SRC   4096
#define N_TOTAL 4096

static constexpr int BM = 128, BN = 128, BK = 32;     // CTA tile
static constexpr int NSTAGES = 4;
static constexpr int KTILES = K_SRC / BK;             // 128
static constexpr int A_STAGE = BM * BK * 2;           // 8192 B
static constexpr int B_STAGE = BK * BN * 2;           // 8192 B
static constexpr int STAGE = A_STAGE + B_STAGE;       // 16384 B
static constexpr int SMEM_BYTES = NSTAGES * STAGE;    // 65536 B

// fp16 scratch (device globals: sanctioned no-alloc workaround)
__device__ __align__(16) __half g_A[(size_t)M_TOTAL * K_SRC];   // 64 MB
__device__ __align__(16) __half g_Bw[(size_t)K_SRC * N_TOTAL];  // 32 MB

// ---------------------------------------------------------------------------
__device__ __forceinline__ uint32_t sw64(uint32_t o)  { return o ^ ((o >> 3) & 0x30); }
__device__ __forceinline__ uint32_t sw128(uint32_t o) { return o ^ ((o >> 3) & 0x70); }

__device__ __forceinline__ uint32_t smem_u32(const void* p) {
    return (uint32_t)__cvta_generic_to_shared(p);
}

__device__ __forceinline__ void cp_async16(uint32_t dst, const void* src) {
    asm volatile("cp.async.cg.shared.global [%0], [%1], 16;"
                 :: "r"(dst), "l"(src) : "memory");
}
__device__ __forceinline__ void cp_commit() {
    asm volatile("cp.async.commit_group;" ::: "memory");
}
template <int N>
__device__ __forceinline__ void cp_wait() {
    asm volatile("cp.async.wait_group %0;" :: "n"(N) : "memory");
}

__device__ __forceinline__ void ldsm_x4(uint32_t* r, uint32_t addr) {
    asm volatile("ldmatrix.sync.aligned.m8n8.x4.shared.b16 {%0,%1,%2,%3}, [%4];"
                 : "=r"(r[0]), "=r"(r[1]), "=r"(r[2]), "=r"(r[3]) : "r"(addr));
}
__device__ __forceinline__ void ldsm_x4_t(uint32_t* r, uint32_t addr) {
    asm volatile("ldmatrix.sync.aligned.m8n8.x4.trans.shared.b16 {%0,%1,%2,%3}, [%4];"
                 : "=r"(r[0]), "=r"(r[1]), "=r"(r[2]), "=r"(r[3]) : "r"(addr));
}

__device__ __forceinline__ void mma16816(float* d, const uint32_t* a, const uint32_t* b) {
    asm volatile(
        "mma.sync.aligned.m16n8k16.row.col.f32.f16.f16.f32 "
        "{%0,%1,%2,%3}, {%4,%5,%6,%7}, {%8,%9}, {%0,%1,%2,%3};"
        : "+f"(d[0]), "+f"(d[1]), "+f"(d[2]), "+f"(d[3])
        : "r"(a[0]), "r"(a[1]), "r"(a[2]), "r"(a[3]), "r"(b[0]), "r"(b[1]));
}

// ---------------------------------------------------------------------------
// prep: x f32 -> fp16 (same layout)
__global__ void prep_x_kernel(const float* __restrict__ x) {
    size_t i = ((size_t)blockIdx.x * 256 + threadIdx.x) * 8;
    float4 a = *reinterpret_cast<const float4*>(x + i);
    float4 b = *reinterpret_cast<const float4*>(x + i + 4);
    __half2 h[4];
    h[0] = __floats2half2_rn(a.x, a.y);
    h[1] = __floats2half2_rn(a.z, a.w);
    h[2] = __floats2half2_rn(b.x, b.y);
    h[3] = __floats2half2_rn(b.z, b.w);
    *reinterpret_cast<uint4*>(g_A + i) = *reinterpret_cast<uint4*>(h);
}

// prep: W f32 -> ternarized fp16 (same [k][n] layout)
__global__ void prep_w_kernel(const float* __restrict__ W) {
    size_t i = ((size_t)blockIdx.x * 256 + threadIdx.x) * 8;
    float4 a = *reinterpret_cast<const float4*>(W + i);
    float4 b = *reinterpret_cast<const float4*>(W + i + 4);
    float v[8] = {a.x, a.y, a.z, a.w, b.x, b.y, b.z, b.w};
    __half hv[8];
    #pragma unroll
    for (int j = 0; j < 8; j++) {
        float t = (v[j] > 0.5f) ? 1.0f : ((v[j] < -0.5f) ? -1.0f : 0.0f);
        hv[j] = __float2half_rn(t);
    }
    *reinterpret_cast<uint4*>(g_Bw + i) = *reinterpret_cast<uint4*>(hv);
}

// ---------------------------------------------------------------------------
// GEMM: CTA 128x128, 8 warps (2x4), warp 64x32, 4-stage cp.async pipeline.
// A smem: [128 m][32 k] fp16, 64B rows, sw64 swizzle.
// B smem: [32 k][128 n] fp16 as two 64-col halves, 128B rows, sw128 swizzle.
// ---------------------------------------------------------------------------
__global__ void __launch_bounds__(256, 2)
gemm_kernel(const float* __restrict__ scale, const float* __restrict__ bias,
            float* __restrict__ out) {
    extern __shared__ unsigned char smem[];
    const uint32_t sbase = smem_u32(smem);

    const int tid  = threadIdx.x;
    const int wid  = tid >> 5;
    const int lane = tid & 31;
    const int wm = wid >> 2;      // 0..1
    const int wn = wid & 3;       // 0..3

    // raster: 8 supergroups x (8 mb x 32 nb); ~40MB live set in L2
    const int bid = blockIdx.x;           // 0..2047
    const int grp = bid >> 8;             // 0..7
    const int loc = bid & 255;
    const int mb  = grp * 8 + (loc & 7);  // 0..63
    const int nbk = loc >> 3;             // 0..31
    const size_t m0 = (size_t)mb * BM;
    const size_t n0 = (size_t)nbk * BN;

    // --- cp.async assignments (2 A-chunks + 2 B-chunks per thread per stage)
    uint32_t a_dst[2], b_dst[2];
    size_t   a_src[2], b_src[2];
    #pragma unroll
    for (int i = 0; i < 2; i++) {
        int id = tid + i * 256;
        int am = id >> 2, ac = id & 3;                 // A: 128 rows x 4 chunks
        a_dst[i] = sw64((uint32_t)(am * 64 + ac * 16));
        a_src[i] = (m0 + am) * K_SRC + ac * 8;
        int bk = id >> 4, nc = id & 15;                // B: 32 rows x 16 chunks
        b_dst[i] = (uint32_t)A_STAGE + (nc >> 3) * 4096 +
                   sw128((uint32_t)(bk * 128 + (nc & 7) * 16));
        b_src[i] = (size_t)bk * N_TOTAL + n0 + nc * 8;
    }

    float d[4][4][4];
    #pragma unroll
    for (int im = 0; im < 4; im++)
        #pragma unroll
        for (int jn = 0; jn < 4; jn++)
            #pragma unroll
            for (int c = 0; c < 4; c++) d[im][jn][c] = 0.0f;

    // --- ldmatrix addresses (per-lane, stage-relative)
    // A: m-block im, kstep j: row = wm*64+im*16+(lane%16), chunk = j*2+(lane/16)
    uint32_t a_addr[4][2];
    #pragma unroll
    for (int im = 0; im < 4; im++)
        #pragma unroll
        for (int j = 0; j < 2; j++) {
            int row = wm * 64 + im * 16 + (lane & 15);
            int kc  = j * 2 + (lane >> 4);
            a_addr[im][j] = sw64((uint32_t)(row * 64 + kc * 16));
        }
    // B: n-pair jn2, kstep j: group g=lane/8: krow = j*16+(g&1)*8+(lane%8),
    // ncol = wn*32 + jn2*16 + (g>>1)*8
    uint32_t b_addr[2][2];
    #pragma unroll
    for (int jn2 = 0; jn2 < 2; jn2++)
        #pragma unroll
        for (int j = 0; j < 2; j++) {
            int g    = lane >> 3;
            int krow = j * 16 + (g & 1) * 8 + (lane & 7);
            int ncol = wn * 32 + jn2 * 16 + (g >> 1) * 8;
            b_addr[jn2][j] = (uint32_t)A_STAGE + (ncol >> 6) * 4096 +
                             sw128((uint32_t)(krow * 128 + (ncol & 63) * 2));
        }

    // --- prologue: load stages 0..2
    #pragma unroll
    for (int kt = 0; kt < NSTAGES - 1; kt++) {
        uint32_t st = sbase + kt * STAGE;
        #pragma unroll
        for (int i = 0; i < 2; i++) {
            cp_async16(st + a_dst[i], g_A + a_src[i] + (size_t)kt * BK);
            cp_async16(st + b_dst[i], g_Bw + b_src[i] + (size_t)kt * BK * N_TOTAL);
        }
        cp_commit();
    }

    // --- mainloop
    int s = 0;
    for (int kt = 0; kt < KTILES; kt++) {
        cp_wait<NSTAGES - 2>();
        __syncthreads();

        const uint32_t st = sbase + s * STAGE;
        #pragma unroll
        for (int j = 0; j < 2; j++) {
            uint32_t a[4][4], b[2][4];
            #pragma unroll
            for (int im = 0; im < 4; im++) ldsm_x4(a[im], st + a_addr[im][j]);
            #pragma unroll
            for (int jn2 = 0; jn2 < 2; jn2++) ldsm_x4_t(b[jn2], st + b_addr[jn2][j]);
            #pragma unroll
            for (int im = 0; im < 4; im++)
                #pragma unroll
                for (int jn = 0; jn < 4; jn++)
                    mma16816(d[im][jn], a[im], &b[jn >> 1][(jn & 1) * 2]);
        }
        __syncthreads();

        const int ktn = kt + NSTAGES - 1;
        if (ktn < KTILES) {
            uint32_t stn = sbase + ((s + NSTAGES - 1) % NSTAGES) * STAGE;
            #pragma unroll
            for (int i = 0; i < 2; i++) {
                cp_async16(stn + a_dst[i], g_A + a_src[i] + (size_t)ktn * BK);
                cp_async16(stn + b_dst[i], g_Bw + b_src[i] + (size_t)ktn * BK * N_TOTAL);
            }
        }
        cp_commit();
        s = (s + 1) & (NSTAGES - 1);
    }

    // --- epilogue: scale/bias/clip, fused
    #pragma unroll
    for (int im = 0; im < 4; im++) {
        const size_t r0 = m0 + wm * 64 + im * 16 + (lane >> 2);
        #pragma unroll
        for (int jn = 0; jn < 4; jn++) {
            const size_t n = n0 + wn * 32 + jn * 8 + (lane & 3) * 2;
            float2 sc = *reinterpret_cast<const float2*>(scale + n);
            float2 bz = *reinterpret_cast<const float2*>(bias + n);
            float2 v0, v1;
            v0.x = fminf(fmaxf(fmaf(d[im][jn][0], sc.x, bz.x), -100.0f), 100.0f);
            v0.y = fminf(fmaxf(fmaf(d[im][jn][1], sc.y, bz.y), -100.0f), 100.0f);
            v1.x = fminf(fmaxf(fmaf(d[im][jn][2], sc.x, bz.x), -100.0f), 100.0f);
            v1.y = fminf(fmaxf(fmaf(d[im][jn][3], sc.y, bz.y), -100.0f), 100.0f);
            *reinterpret_cast<float2*>(out + r0 * N_TOTAL + n) = v0;
            *reinterpret_cast<float2*>(out + (r0 + 8) * N_TOTAL + n) = v1;
        }
    }
}

// ---------------------------------------------------------------------------
extern "C" void kernel_launch(void* const* d_in, const int* in_sizes, int n_in,
                              void* d_out, int out_size) {
    (void)in_sizes; (void)n_in; (void)out_size;
    const float* x     = (const float*)d_in[0];
    const float* W     = (const float*)d_in[1];
    const float* scale = (const float*)d_in[2];
    const float* bias  = (const float*)d_in[3];
    float* out = (float*)d_out;

    cudaFuncSetAttribute(gemm_kernel, cudaFuncAttributeMaxDynamicSharedMemorySize,
                         SMEM_BYTES);

    prep_x_kernel<<<(M_TOTAL * (size_t)K_SRC) / (256 * 8), 256>>>(x);
    prep_w_kernel<<<(K_SRC * (size_t)N_TOTAL) / (256 * 8), 256>>>(W);
    gemm_kernel<<<(M_TOTAL / BM) * (N_TOTAL / BN), 256, SMEM_BYTES>>>(scale, bias, out);
}

// round 17
// speedup vs baseline: 1.0030x; 1.0030x over previous
#include <cuda_runtime.h>
#include <cuda_fp16.h>
#include <cstdint>
#include <cstddef>

// ============================================================================
// y = clip((x @ ternarize(W)) * scale + bias, -100, 100)
//   x [8192,4096] f32, W [4096,4096] f32, scale/bias [4096] f32, out f32.
//
// mma.sync m16n8k16 fp16 (compute_103 baseline; tcgen05 unavailable in this
// harness). R9 baseline: 644us. This round: BK=64, 3 stages, single-sync
// mainloop with loads issued before compute (CUTLASS multistage ordering).
// ============================================================================

#define M_TOTAL 8192
#define K_SRC   4096
#define N_TOTAL 4096

static constexpr int BM = 128, BN = 128, BK = 64;     // CTA tile
static constexpr int NSTAGES = 3;
static constexpr int KTILES = K_SRC / BK;             // 64
static constexpr int A_STAGE = BM * BK * 2;           // 16384 B
static constexpr int B_STAGE = BK * BN * 2;           // 16384 B
static constexpr int STAGE = A_STAGE + B_STAGE;       // 32768 B
static constexpr int SMEM_BYTES = NSTAGES * STAGE;    // 98304 B (occ 2: 192KB)

// fp16 scratch (device globals: sanctioned no-alloc workaround)
__device__ __align__(16) __half g_A[(size_t)M_TOTAL * K_SRC];   // 64 MB
__device__ __align__(16) __half g_Bw[(size_t)K_SRC * N_TOTAL];  // 32 MB

// ---------------------------------------------------------------------------
__device__ __forceinline__ uint32_t sw128(uint32_t o) { return o ^ ((o >> 3) & 0x70); }

__device__ __forceinline__ uint32_t smem_u32(const void* p) {
    return (uint32_t)__cvta_generic_to_shared(p);
}

__device__ __forceinline__ void cp_async16(uint32_t dst, const void* src) {
    asm volatile("cp.async.cg.shared.global [%0], [%1], 16;"
                 :: "r"(dst), "l"(src) : "memory");
}
__device__ __forceinline__ void cp_commit() {
    asm volatile("cp.async.commit_group;" ::: "memory");
}
template <int N>
__device__ __forceinline__ void cp_wait() {
    asm volatile("cp.async.wait_group %0;" :: "n"(N) : "memory");
}

__device__ __forceinline__ void ldsm_x4(uint32_t* r, uint32_t addr) {
    asm volatile("ldmatrix.sync.aligned.m8n8.x4.shared.b16 {%0,%1,%2,%3}, [%4];"
                 : "=r"(r[0]), "=r"(r[1]), "=r"(r[2]), "=r"(r[3]) : "r"(addr));
}
__device__ __forceinline__ void ldsm_x4_t(uint32_t* r, uint32_t addr) {
    asm volatile("ldmatrix.sync.aligned.m8n8.x4.trans.shared.b16 {%0,%1,%2,%3}, [%4];"
                 : "=r"(r[0]), "=r"(r[1]), "=r"(r[2]), "=r"(r[3]) : "r"(addr));
}

__device__ __forceinline__ void mma16816(float* d, const uint32_t* a, const uint32_t* b) {
    asm volatile(
        "mma.sync.aligned.m16n8k16.row.col.f32.f16.f16.f32 "
        "{%0,%1,%2,%3}, {%4,%5,%6,%7}, {%8,%9}, {%0,%1,%2,%3};"
        : "+f"(d[0]), "+f"(d[1]), "+f"(d[2]), "+f"(d[3])
        : "r"(a[0]), "r"(a[1]), "r"(a[2]), "r"(a[3]), "r"(b[0]), "r"(b[1]));
}

// ---------------------------------------------------------------------------
// prep: x f32 -> fp16 (same layout)
__global__ void prep_x_kernel(const float* __restrict__ x) {
    size_t i = ((size_t)blockIdx.x * 256 + threadIdx.x) * 8;
    float4 a = *reinterpret_cast<const float4*>(x + i);
    float4 b = *reinterpret_cast<const float4*>(x + i + 4);
    __half2 h[4];
    h[0] = __floats2half2_rn(a.x, a.y);
    h[1] = __floats2half2_rn(a.z, a.w);
    h[2] = __floats2half2_rn(b.x, b.y);
    h[3] = __floats2half2_rn(b.z, b.w);
    *reinterpret_cast<uint4*>(g_A + i) = *reinterpret_cast<uint4*>(h);
}

// prep: W f32 -> ternarized fp16 (same [k][n] layout)
__global__ void prep_w_kernel(const float* __restrict__ W) {
    size_t i = ((size_t)blockIdx.x * 256 + threadIdx.x) * 8;
    float4 a = *reinterpret_cast<const float4*>(W + i);
    float4 b = *reinterpret_cast<const float4*>(W + i + 4);
    float v[8] = {a.x, a.y, a.z, a.w, b.x, b.y, b.z, b.w};
    __half hv[8];
    #pragma unroll
    for (int j = 0; j < 8; j++) {
        float t = (v[j] > 0.5f) ? 1.0f : ((v[j] < -0.5f) ? -1.0f : 0.0f);
        hv[j] = __float2half_rn(t);
    }
    *reinterpret_cast<uint4*>(g_Bw + i) = *reinterpret_cast<uint4*>(hv);
}

// ---------------------------------------------------------------------------
// GEMM: CTA 128x128, 8 warps (2x4), warp 64x32, BK=64, 3-stage single-sync.
// A smem: [128 m][64 k] fp16, 128B rows, sw128.
// B smem: [64 k][128 n] fp16 as two 64-col halves (8KB each), 128B rows, sw128.
// ---------------------------------------------------------------------------
__global__ void __launch_bounds__(256, 2)
gemm_kernel(const float* __restrict__ scale, const float* __restrict__ bias,
            float* __restrict__ out) {
    extern __shared__ unsigned char smem[];
    const uint32_t sbase = smem_u32(smem);

    const int tid  = threadIdx.x;
    const int wid  = tid >> 5;
    const int lane = tid & 31;
    const int wm = wid >> 2;      // 0..1
    const int wn = wid & 3;       // 0..3

    // raster: 8 supergroups x (8 mb x 32 nb); ~40MB live set in L2
    const int bid = blockIdx.x;           // 0..2047
    const int grp = bid >> 8;             // 0..7
    const int loc = bid & 255;
    const int mb  = grp * 8 + (loc & 7);  // 0..63
    const int nbk = loc >> 3;             // 0..31
    const size_t m0 = (size_t)mb * BM;
    const size_t n0 = (size_t)nbk * BN;

    // --- cp.async assignments (4 A-chunks + 4 B-chunks per thread per stage)
    uint32_t a_dst[4], b_dst[4];
    uint32_t a_src[4], b_src[4];   // element offsets into g_A / g_Bw (fit 32b)
    #pragma unroll
    for (int i = 0; i < 4; i++) {
        int id = tid + i * 256;                       // 0..1023
        int am = id >> 3, ac = id & 7;                // A: 128 rows x 8 chunks
        a_dst[i] = sw128((uint32_t)(am * 128 + ac * 16));
        a_src[i] = (uint32_t)((m0 + am) * K_SRC + ac * 8);
        int bk = id >> 4, nc = id & 15;               // B: 64 rows x 16 chunks
        b_dst[i] = (uint32_t)A_STAGE + (nc >> 3) * 8192 +
                   sw128((uint32_t)(bk * 128 + (nc & 7) * 16));
        b_src[i] = (uint32_t)((size_t)bk * N_TOTAL + n0 + nc * 8);
    }

    float d[4][4][4];
    #pragma unroll
    for (int im = 0; im < 4; im++)
        #pragma unroll
        for (int jn = 0; jn < 4; jn++)
            #pragma unroll
            for (int c = 0; c < 4; c++) d[im][jn][c] = 0.0f;

    // --- ldmatrix base addresses (j=0); per-kstep j: A ^= j<<5, B += j*2048.
    uint32_t a_addr[4];
    #pragma unroll
    for (int im = 0; im < 4; im++) {
        int row = wm * 64 + im * 16 + (lane & 15);
        int kc0 = lane >> 4;                          // 0..1
        a_addr[im] = sw128((uint32_t)(row * 128 + kc0 * 16));
    }
    uint32_t b_addr[2];
    #pragma unroll
    for (int jn2 = 0; jn2 < 2; jn2++) {
        int g    = lane >> 3;
        int krow = (g & 1) * 8 + (lane & 7);          // j=0 block
        int ncol = wn * 32 + jn2 * 16 + (g >> 1) * 8;
        b_addr[jn2] = (uint32_t)A_STAGE + (ncol >> 6) * 8192 +
                      sw128((uint32_t)(krow * 128 + (ncol & 63) * 2));
    }

    // --- prologue: stages 0..1
    #pragma unroll
    for (int kt = 0; kt < NSTAGES - 1; kt++) {
        uint32_t st = sbase + kt * STAGE;
        #pragma unroll
        for (int i = 0; i < 4; i++)
            cp_async16(st + a_dst[i], g_A + a_src[i] + (size_t)kt * BK);
        #pragma unroll
        for (int i = 0; i < 4; i++)
            cp_async16(st + b_dst[i], g_Bw + b_src[i] + (size_t)kt * BK * N_TOTAL);
        cp_commit();
    }

    // --- mainloop: single sync; loads lead compute.
    int s = 0;
    for (int kt = 0; kt < KTILES; kt++) {
        cp_wait<NSTAGES - 2>();
        __syncthreads();   // guards RAW on stage s AND WAR on stage s+2 (== s-1)

        const int ktn = kt + NSTAGES - 1;
        if (ktn < KTILES) {
            uint32_t stn = sbase + ((s + NSTAGES - 1) % NSTAGES) * STAGE;
            #pragma unroll
            for (int i = 0; i < 4; i++)
                cp_async16(stn + a_dst[i], g_A + a_src[i] + (size_t)ktn * BK);
            #pragma unroll
            for (int i = 0; i < 4; i++)
                cp_async16(stn + b_dst[i], g_Bw + b_src[i] + (size_t)ktn * BK * N_TOTAL);
        }
        cp_commit();

        const uint32_t st = sbase + s * STAGE;
        #pragma unroll
        for (int j = 0; j < 4; j++) {
            uint32_t a[4][4], b[2][4];
            #pragma unroll
            for (int im = 0; im < 4; im++)
                ldsm_x4(a[im], st + (a_addr[im] ^ (uint32_t)(j << 5)));
            #pragma unroll
            for (int jn2 = 0; jn2 < 2; jn2++)
                ldsm_x4_t(b[jn2], st + b_addr[jn2] + (uint32_t)(j * 2048));
            #pragma unroll
            for (int im = 0; im < 4; im++)
                #pragma unroll
                for (int jn = 0; jn < 4; jn++)
                    mma16816(d[im][jn], a[im], &b[jn >> 1][(jn & 1) * 2]);
        }
        if (++s == NSTAGES) s = 0;
    }

    // --- epilogue: scale/bias/clip, fused
    #pragma unroll
    for (int im = 0; im < 4; im++) {
        const size_t r0 = m0 + wm * 64 + im * 16 + (lane >> 2);
        #pragma unroll
        for (int jn = 0; jn < 4; jn++) {
            const size_t n = n0 + wn * 32 + jn * 8 + (lane & 3) * 2;
            float2 sc = *reinterpret_cast<const float2*>(scale + n);
            float2 bz = *reinterpret_cast<const float2*>(bias + n);
            float2 v0, v1;
            v0.x = fminf(fmaxf(fmaf(d[im][jn][0], sc.x, bz.x), -100.0f), 100.0f);
            v0.y = fminf(fmaxf(fmaf(d[im][jn][1], sc.y, bz.y), -100.0f), 100.0f);
            v1.x = fminf(fmaxf(fmaf(d[im][jn][2], sc.x, bz.x), -100.0f), 100.0f);
            v1.y = fminf(fmaxf(fmaf(d[im][jn][3], sc.y, bz.y), -100.0f), 100.0f);
            *reinterpret_cast<float2*>(out + r0 * N_TOTAL + n) = v0;
            *reinterpret_cast<float2*>(out + (r0 + 8) * N_TOTAL + n) = v1;
        }
    }
}

// ---------------------------------------------------------------------------
extern "C" void kernel_launch(void* const* d_in, const int* in_sizes, int n_in,
                              void* d_out, int out_size) {
    (void)in_sizes; (void)n_in; (void)out_size;
    const float* x     = (const float*)d_in[0];
    const float* W     = (const float*)d_in[1];
    const float* scale = (const float*)d_in[2];
    const float* bias  = (const float*)d_in[3];
    float* out = (float*)d_out;

    cudaFuncSetAttribute(gemm_kernel, cudaFuncAttributeMaxDynamicSharedMemorySize,
                         SMEM_BYTES);

    prep_x_kernel<<<(M_TOTAL * (size_t)K_SRC) / (256 * 8), 256>>>(x);
    prep_w_kernel<<<(K_SRC * (size_t)N_TOTAL) / (256 * 8), 256>>>(W);
    gemm_kernel<<<(M_TOTAL / BM) * (N_TOTAL / BN), 256, SMEM_BYTES>>>(scale, bias, out);
}